// round 16
// baseline (speedup 1.0000x reference)
#include <cuda_runtime.h>
#include <cstdint>

#define BATCH 8
#define NPTS  4096
#define MPTS  2048
#define FDIM  64
#define KNBR  64
#define NG    (BATCH*MPTS)
#define CAP   256
#define NTICK (NG/2)
#define NTHR  512

// output segments (float32): x_out [NG,128] | pos_out [NG,3] | batch_out [NG]
#define XSEG   (NG*128)
#define PBASE  XSEG
#define BBASE  (XSEG + NG*3)
#define TOTSEG (BBASE + NG)

__device__ float  g_q[NG*3];
__device__ float4 g_pos4[BATCH*NPTS];
__device__ volatile int g_prog[BATCH];
__device__ int    g_ctr;

typedef unsigned long long u64;

__device__ __forceinline__ unsigned rmax32(unsigned v) {
    unsigned r;
    asm("redux.sync.max.u32 %0, %1, 0xffffffff;" : "=r"(r) : "r"(v));
    return r;
}
__device__ __forceinline__ u64 pk2(float lo, float hi) {
    u64 r; asm("mov.b64 %0, {%1, %2};" : "=l"(r) : "f"(lo), "f"(hi)); return r;
}
__device__ __forceinline__ void up2(u64 v, float& lo, float& hi) {
    asm("mov.b64 {%0, %1}, %2;" : "=f"(lo), "=f"(hi) : "l"(v));
}
__device__ __forceinline__ u64 fma2(u64 a, u64 b, u64 c) {
    u64 r; asm("fma.rn.f32x2 %0, %1, %2, %3;" : "=l"(r) : "l"(a), "l"(b), "l"(c)); return r;
}
__device__ __forceinline__ void cp16(uint32_t dst, const float4* src) {
    asm volatile("cp.async.cg.shared.global [%0], [%1], 16;" :: "r"(dst), "l"(src));
}
#define CP_COMMIT() asm volatile("cp.async.commit_group;" ::: "memory")
#define CP_WAIT0()  asm volatile("cp.async.wait_group 0;"  ::: "memory")
__device__ __forceinline__ float ldcv(const float* p) {
    float v; asm volatile("ld.global.cv.f32 %0, [%1];" : "=f"(v) : "l"(p)); return v;
}

// ---------------- smem layout (floats) ----------------
#define W1T 0          // 64 x 70   W1t[c*70+k] = W1[k*64+c]
#define W2T 4480       // 64 x 66
#define W3T 8704       // 128 x 66
#define B1O 17152
#define B2O 17216
#define B3O 17280
#define F0  17408      // item0 feat 64x68
#define F1  21760      // item1 feat 64x68
#define H1A 26112      // 64x66
#define H1B 30336
#define H2A 34560
#define H2B 38784
#define RO0 43008      // 32x128
#define RO1 47104      // 32x128
#define CD0 51200      // 256
#define CI0 51456      // 256 int
#define CD1 51712
#define CI1 51968
#define NL0 52224      // 64 int
#define NL1 52288      // 64 int
#define MS  52352      // ints [0]=seq [1]=cnt0 [2]=cnt1; floats +4..9 = q0,q1
#define SM_TOT 52368   // 209,472 bytes -> 1 CTA/SM

// ============================================================================
__global__ void __launch_bounds__(256)
init_kernel(const float* __restrict__ pos)
{
    int i = blockIdx.x * 256 + threadIdx.x;
    if (i == 0) g_ctr = 0;
    if (i < BATCH) g_prog[i] = 0;
    if (i < BATCH * NPTS) {
        const float* p = pos + (size_t)i * 3;
        g_pos4[i] = make_float4(p[0], p[1], p[2], 0.0f);
    }
}

// ============================================================================
__global__ void __launch_bounds__(NTHR)
fused_kernel(const float* __restrict__ x, const float* __restrict__ pos,
             const float* __restrict__ W1, const float* __restrict__ b1,
             const float* __restrict__ W2, const float* __restrict__ b2,
             const float* __restrict__ W3, const float* __restrict__ b3,
             float* __restrict__ dout, int out_size)
{
    extern __shared__ float sm[];
    const int tid = threadIdx.x;
    const int lane = tid & 31, w = tid >> 5;

    // ======================= producer: FPS (blocks 0..7, 512 thr) ==========
    if (blockIdx.x < BATCH) {
        __shared__ u64 rd2[32];                 // [parity*16 + warp]
        float* sp = sm;                         // compact stride-3 pos cache
        const int b = blockIdx.x;
        const float* pb = pos + (size_t)b * NPTS * 3;

        for (int i = tid; i < NPTS * 3; i += NTHR) sp[i] = pb[i];
        __syncthreads();

        float px[8], py[8], pz[8], md[8];
#pragma unroll
        for (int j = 0; j < 8; j++) {
            int idx = j * 512 + tid;
            px[j] = sp[3*idx]; py[j] = sp[3*idx+1]; pz[j] = sp[3*idx+2];
            md[j] = __int_as_float(0x7f800000);
        }

        if (tid == 0) {
            int g = b * MPTS;
            g_q[3*g] = sp[0]; g_q[3*g+1] = sp[1]; g_q[3*g+2] = sp[2];
            if (out_size >= BBASE) {
                dout[PBASE+3*g] = sp[0]; dout[PBASE+3*g+1] = sp[1]; dout[PBASE+3*g+2] = sp[2];
            }
            if (out_size >= TOTSEG) dout[BBASE+g] = (float)b;
            __threadfence();
            g_prog[b] = 1;
        }
        __syncthreads();

        int cur = 0;
        for (int step = 1; step < MPTS; step++) {
            float lx = sp[3*cur], ly = sp[3*cur+1], lz = sp[3*cur+2];
            float bd = -1.0f; int bi = 0;
#pragma unroll
            for (int j = 0; j < 8; j++) {
                float dx = __fadd_rn(px[j], -lx);
                float dy = __fadd_rn(py[j], -ly);
                float dz = __fadd_rn(pz[j], -lz);
                float d  = __fadd_rn(__fadd_rn(__fmul_rn(dx,dx), __fmul_rn(dy,dy)),
                                     __fmul_rn(dz,dz));
                float m = fminf(md[j], d);
                md[j] = m;
                if (m > bd) { bd = m; bi = j * 512 + tid; }
            }
            unsigned dbits = __float_as_uint(bd);
            unsigned mx   = rmax32(dbits);
            unsigned cand = (dbits == mx) ? (0xFFFFFFFFu - (unsigned)bi) : 0u;
            unsigned cmx  = rmax32(cand);
            if (lane == 0) rd2[(step & 1) * 16 + w] = ((u64)mx << 32) | (u64)cmx;
            __syncthreads();
            const u64* rr = &rd2[(step & 1) * 16];
            u64 best = rr[0];
#pragma unroll
            for (int i = 1; i < 16; i++) { u64 v = rr[i]; if (v > best) best = v; }
            cur = (int)(0xFFFFFFFFu - (unsigned)best);
            if (tid == 0) {
                int g = b * MPTS + step;
                float qx = sp[3*cur], qy = sp[3*cur+1], qz = sp[3*cur+2];
                g_q[3*g] = qx; g_q[3*g+1] = qy; g_q[3*g+2] = qz;
                if (out_size >= BBASE) {
                    dout[PBASE+3*g] = qx; dout[PBASE+3*g+1] = qy; dout[PBASE+3*g+2] = qz;
                }
                if (out_size >= TOTSEG) dout[BBASE+g] = (float)b;
                __threadfence();
                g_prog[b] = step + 1;
            }
        }
        __syncthreads();
    }

    // ======================= consumer setup =================================
    for (int idx = tid; idx < 67 * 64; idx += NTHR) {
        int k = idx >> 6, c = idx & 63;
        sm[W1T + c * 70 + k] = W1[idx];
    }
    for (int idx = tid; idx < 64 * 64; idx += NTHR) {
        int k = idx >> 6, c = idx & 63;
        sm[W2T + c * 66 + k] = W2[idx];
    }
    for (int idx = tid; idx < 64 * 128; idx += NTHR) {
        int k = idx >> 7, c = idx & 127;
        sm[W3T + c * 66 + k] = W3[idx];
    }
    if (tid < 64)  { sm[B1O + tid] = b1[tid]; sm[B2O + tid] = b2[tid]; }
    if (tid < 128)   sm[B3O + tid] = b3[tid];
    __syncthreads();

    int*   msi = (int*)(sm + MS);
    float* msf = sm + MS + 4;
    int*   nl0 = (int*)(sm + NL0);
    int*   nl1 = (int*)(sm + NL1);
    int*   ci0 = (int*)(sm + CI0);
    int*   ci1 = (int*)(sm + CI1);

    const int rg = tid >> 4;     // 0..31: rows 2rg, 2rg+1
    const int cg = tid & 15;     // 0..15
    const int e = tid >> 3, sub = tid & 7;      // gather: row e, 8 threads/row
    const uint32_t smF0 = (uint32_t)__cvta_generic_to_shared(sm + F0);
    const uint32_t smF1 = (uint32_t)__cvta_generic_to_shared(sm + F1);
    const uint32_t rowoff = (uint32_t)((e * 68 + sub * 8) * sizeof(float));
    const float R2 = (float)(0.15 * 0.15);

    for (;;) {
        if (tid == 0) msi[0] = atomicAdd(&g_ctr, 1);
        __syncthreads();
        const int t = msi[0];
        if (t >= NTICK) break;
        const int b = t & 7, m0 = (t >> 3) * 2, m1 = m0 + 1;
        const int g0 = b * MPTS + m0, g1 = g0 + 1;

        if (tid == 0) {
            while (g_prog[b] <= m1) __nanosleep(128);
            __threadfence();
            msf[0] = ldcv(&g_q[3*g0]);
            msf[1] = ldcv(&g_q[3*g0+1]);
            msf[2] = ldcv(&g_q[3*g0+2]);
            msf[3] = ldcv(&g_q[3*g1]);
            msf[4] = ldcv(&g_q[3*g1+1]);
            msf[5] = ldcv(&g_q[3*g1+2]);
            msi[1] = 0; msi[2] = 0;
        }
        __syncthreads();
        const float q0x = msf[0], q0y = msf[1], q0z = msf[2];
        const float q1x = msf[3], q1y = msf[4], q1z = msf[5];

        // ---- radius scan: one pass, both centroids (8 iters) ----
#pragma unroll 2
        for (int i = tid; i < NPTS; i += NTHR) {
            float4 p = g_pos4[b * NPTS + i];
            float dx0 = __fadd_rn(q0x, -p.x);
            float dy0 = __fadd_rn(q0y, -p.y);
            float dz0 = __fadd_rn(q0z, -p.z);
            float d20 = __fadd_rn(__fadd_rn(__fmul_rn(dx0,dx0), __fmul_rn(dy0,dy0)),
                                  __fmul_rn(dz0,dz0));
            float dx1 = __fadd_rn(q1x, -p.x);
            float dy1 = __fadd_rn(q1y, -p.y);
            float dz1 = __fadd_rn(q1z, -p.z);
            float d21 = __fadd_rn(__fadd_rn(__fmul_rn(dx1,dx1), __fmul_rn(dy1,dy1)),
                                  __fmul_rn(dz1,dz1));
            bool k0 = (d20 <= R2);
            unsigned msk0 = __ballot_sync(0xffffffffu, k0);
            int base0 = 0;
            if (lane == 0 && msk0) base0 = atomicAdd(&msi[1], __popc(msk0));
            base0 = __shfl_sync(0xffffffffu, base0, 0);
            if (k0) {
                int ofs = base0 + __popc(msk0 & ((1u << lane) - 1u));
                if (ofs < CAP) { sm[CD0 + ofs] = d20; ci0[ofs] = i; }
            }
            bool k1 = (d21 <= R2);
            unsigned msk1 = __ballot_sync(0xffffffffu, k1);
            int base1 = 0;
            if (lane == 0 && msk1) base1 = atomicAdd(&msi[2], __popc(msk1));
            base1 = __shfl_sync(0xffffffffu, base1, 0);
            if (k1) {
                int ofs = base1 + __popc(msk1 & ((1u << lane) - 1u));
                if (ofs < CAP) { sm[CD1 + ofs] = d21; ci1[ofs] = i; }
            }
        }
        __syncthreads();
        int cnt0 = msi[1]; if (cnt0 > CAP) cnt0 = CAP;
        int cnt1 = msi[2]; if (cnt1 > CAP) cnt1 = CAP;

        // ---- rank-select both items in parallel (256 threads each) ----
        {
            const int item = tid >> 8;           // 0 or 1
            const int ht = tid & 255;
            const int cnt = item ? cnt1 : cnt0;
            const float* cd = sm + (item ? CD1 : CD0);
            const int* cidx = item ? ci1 : ci0;
            int* nlout = item ? nl1 : nl0;
            if (cnt > KNBR) {
                for (int s = ht; s < cnt; s += 256) {
                    float di = cd[s]; int ii = cidx[s];
                    int r = 0;
                    for (int j2 = 0; j2 < cnt; j2++) {
                        float dj = cd[j2];
                        r += (int)((dj < di) | ((dj == di) & (cidx[j2] < ii)));
                    }
                    if (r < KNBR) nlout[r] = ii;
                }
            } else {
                for (int s = ht; s < cnt; s += 256) nlout[s] = cidx[s];
            }
        }
        __syncthreads();
        if (cnt0 > KNBR) cnt0 = KNBR;
        if (cnt1 > KNBR) cnt1 = KNBR;

        // ---- gather both items' feat rows via cp.async (8 thr/row) ----
        {
            int j0 = nl0[(e < cnt0) ? e : 0];
            int j1 = nl1[(e < cnt1) ? e : 0];
            const float4* xr0 = (const float4*)(x + ((size_t)b * NPTS + j0) * FDIM) + sub * 2;
            const float4* xr1 = (const float4*)(x + ((size_t)b * NPTS + j1) * FDIM) + sub * 2;
            cp16(smF0 + rowoff +  0, xr0 + 0);
            cp16(smF0 + rowoff + 16, xr0 + 1);
            cp16(smF1 + rowoff +  0, xr1 + 0);
            cp16(smF1 + rowoff + 16, xr1 + 1);
            CP_COMMIT();
            if (sub == 0) {
                float4 p0 = g_pos4[b * NPTS + j0];
                float4 p1 = g_pos4[b * NPTS + j1];
                float a0 = __fadd_rn(p0.x, -q0x);
                float a1 = __fadd_rn(p0.y, -q0y);
                float a2 = __fadd_rn(p0.z, -q0z);
                float c0 = __fadd_rn(p1.x, -q1x);
                float c1 = __fadd_rn(p1.y, -q1y);
                float c2 = __fadd_rn(p1.z, -q1z);
                CP_WAIT0();
                sm[F0 + e*68 + 64] = a0; sm[F0 + e*68 + 65] = a1; sm[F0 + e*68 + 66] = a2;
                sm[F1 + e*68 + 64] = c0; sm[F1 + e*68 + 65] = c1; sm[F1 + e*68 + 66] = c2;
            } else {
                CP_WAIT0();
            }
        }
        __syncthreads();

        // ---- layer 1 (dual-item, W hoisted, 2 rows/thread): K=67 ----
        {
            u64 acc0[2][4], acc1[2][4];
#pragma unroll
            for (int j = 0; j < 4; j++) {
                float bb = sm[B1O + cg + 16*j];
#pragma unroll
                for (int i = 0; i < 2; i++) {
                    acc0[i][j] = pk2(bb, 0.0f);
                    acc1[i][j] = pk2(bb, 0.0f);
                }
            }
            for (int kp = 0; kp < 33; kp++) {
                const int k = 2 * kp;
                u64 a0[2], a1[2];
#pragma unroll
                for (int i = 0; i < 2; i++) {
                    a0[i] = *(const u64*)(sm + F0 + (2*rg + i)*68 + k);
                    a1[i] = *(const u64*)(sm + F1 + (2*rg + i)*68 + k);
                }
#pragma unroll
                for (int j = 0; j < 4; j++) {
                    u64 wv = *(const u64*)(sm + W1T + (cg + 16*j)*70 + k);
#pragma unroll
                    for (int i = 0; i < 2; i++) {
                        acc0[i][j] = fma2(a0[i], wv, acc0[i][j]);
                        acc1[i][j] = fma2(a1[i], wv, acc1[i][j]);
                    }
                }
            }
#pragma unroll
            for (int i = 0; i < 2; i++) {
                float a66A = sm[F0 + (2*rg + i)*68 + 66];
                float a66B = sm[F1 + (2*rg + i)*68 + 66];
#pragma unroll
                for (int j = 0; j < 4; j++) {
                    float wk = sm[W1T + (cg + 16*j)*70 + 66];
                    float lo, hi;
                    up2(acc0[i][j], lo, hi);
                    float s0 = fmaf(a66A, wk, __fadd_rn(lo, hi));
                    sm[H1A + (2*rg + i)*66 + cg + 16*j] = fmaxf(s0, 0.0f);
                    up2(acc1[i][j], lo, hi);
                    float s1 = fmaf(a66B, wk, __fadd_rn(lo, hi));
                    sm[H1B + (2*rg + i)*66 + cg + 16*j] = fmaxf(s1, 0.0f);
                }
            }
        }
        __syncthreads();

        // ---- layer 2 (dual-item, W hoisted): K=64 ----
        {
            u64 acc0[2][4], acc1[2][4];
#pragma unroll
            for (int j = 0; j < 4; j++) {
                float bb = sm[B2O + cg + 16*j];
#pragma unroll
                for (int i = 0; i < 2; i++) {
                    acc0[i][j] = pk2(bb, 0.0f);
                    acc1[i][j] = pk2(bb, 0.0f);
                }
            }
            for (int kp = 0; kp < 32; kp++) {
                const int k = 2 * kp;
                u64 a0[2], a1[2];
#pragma unroll
                for (int i = 0; i < 2; i++) {
                    a0[i] = *(const u64*)(sm + H1A + (2*rg + i)*66 + k);
                    a1[i] = *(const u64*)(sm + H1B + (2*rg + i)*66 + k);
                }
#pragma unroll
                for (int j = 0; j < 4; j++) {
                    u64 wv = *(const u64*)(sm + W2T + (cg + 16*j)*66 + k);
#pragma unroll
                    for (int i = 0; i < 2; i++) {
                        acc0[i][j] = fma2(a0[i], wv, acc0[i][j]);
                        acc1[i][j] = fma2(a1[i], wv, acc1[i][j]);
                    }
                }
            }
#pragma unroll
            for (int i = 0; i < 2; i++)
#pragma unroll
                for (int j = 0; j < 4; j++) {
                    float lo, hi;
                    up2(acc0[i][j], lo, hi);
                    sm[H2A + (2*rg + i)*66 + cg + 16*j] = fmaxf(__fadd_rn(lo, hi), 0.0f);
                    up2(acc1[i][j], lo, hi);
                    sm[H2B + (2*rg + i)*66 + cg + 16*j] = fmaxf(__fadd_rn(lo, hi), 0.0f);
                }
        }
        __syncthreads();

        // ---- layer 3: per item sequential, K=64, 2 rows x 8 cols ----
#pragma unroll 1
        for (int it = 0; it < 2; it++) {
            const int hsrc = it ? H2B : H2A;
            const int rdst = it ? RO1 : RO0;
            u64 acc[2][8];
#pragma unroll
            for (int j = 0; j < 8; j++) {
                float bb = sm[B3O + cg + 16*j];
#pragma unroll
                for (int i = 0; i < 2; i++) acc[i][j] = pk2(bb, 0.0f);
            }
            for (int kp = 0; kp < 32; kp++) {
                const int k = 2 * kp;
                u64 a[2];
#pragma unroll
                for (int i = 0; i < 2; i++)
                    a[i] = *(const u64*)(sm + hsrc + (2*rg + i)*66 + k);
#pragma unroll
                for (int j = 0; j < 8; j++) {
                    u64 wv = *(const u64*)(sm + W3T + (cg + 16*j)*66 + k);
#pragma unroll
                    for (int i = 0; i < 2; i++)
                        acc[i][j] = fma2(a[i], wv, acc[i][j]);
                }
            }
#pragma unroll
            for (int j = 0; j < 8; j++) {
                float lo, hi; up2(acc[0][j], lo, hi);
                float mm = fmaxf(__fadd_rn(lo, hi), 0.0f);
                up2(acc[1][j], lo, hi);
                mm = fmaxf(mm, fmaxf(__fadd_rn(lo, hi), 0.0f));
                sm[rdst + rg*128 + cg + 16*j] = mm;
            }
        }
        __syncthreads();

        // ---- final reduce + store: tids 0-127 item0, 128-255 item1 ----
        if (tid < 256) {
            const int item = tid >> 7;
            const int ht = tid & 127;
            const int rsrc = item ? RO1 : RO0;
            const int gg = item ? g1 : g0;
            float mm = sm[rsrc + ht];
#pragma unroll
            for (int r = 1; r < 32; r++) mm = fmaxf(mm, sm[rsrc + r*128 + ht]);
            dout[(size_t)gg * 128 + ht] = mm;
        }
        __syncthreads();   // protect smem reuse next iteration
    }
}

// ============================================================================
extern "C" void kernel_launch(void* const* d_in, const int* in_sizes, int n_in,
                              void* d_out, int out_size)
{
    const float* x   = (const float*)d_in[0];
    const float* pos = (const float*)d_in[1];
    const float* W1 = (const float*)d_in[3];
    const float* b1 = (const float*)d_in[4];
    const float* W2 = (const float*)d_in[5];
    const float* b2 = (const float*)d_in[6];
    const float* W3 = (const float*)d_in[7];
    const float* b3 = (const float*)d_in[8];
    float* out = (float*)d_out;

    const int fused_smem = SM_TOT * sizeof(float);   // 209,472 B -> 1 CTA/SM
    cudaFuncSetAttribute(fused_kernel, cudaFuncAttributeMaxDynamicSharedMemorySize,
                         fused_smem);

    init_kernel<<<(BATCH * NPTS + 255) / 256, 256>>>(pos);
    fused_kernel<<<148, NTHR, fused_smem>>>(x, pos, W1, b1, W2, b2, W3, b3,
                                            out, out_size);
}

// round 17
// speedup vs baseline: 1.2519x; 1.2519x over previous
#include <cuda_runtime.h>
#include <cstdint>

#define BATCH 8
#define NPTS  4096
#define MPTS  2048
#define FDIM  64
#define KNBR  64
#define NG    (BATCH*MPTS)
#define CAP   256
#define NTICK (NG/4)

// output segments (float32): x_out [NG,128] | pos_out [NG,3] | batch_out [NG]
#define XSEG   (NG*128)
#define PBASE  XSEG
#define BBASE  (XSEG + NG*3)
#define TOTSEG (BBASE + NG)

__device__ float  g_q[NG*3];
__device__ float4 g_pos4[BATCH*NPTS];
__device__ volatile int g_prog[BATCH];
__device__ int    g_ctr;

typedef unsigned long long u64;

__device__ __forceinline__ unsigned rmax32(unsigned v) {
    unsigned r;
    asm("redux.sync.max.u32 %0, %1, 0xffffffff;" : "=r"(r) : "r"(v));
    return r;
}
__device__ __forceinline__ u64 pk2(float lo, float hi) {
    u64 r; asm("mov.b64 %0, {%1, %2};" : "=l"(r) : "f"(lo), "f"(hi)); return r;
}
__device__ __forceinline__ void up2(u64 v, float& lo, float& hi) {
    asm("mov.b64 {%0, %1}, %2;" : "=f"(lo), "=f"(hi) : "l"(v));
}
__device__ __forceinline__ u64 fma2(u64 a, u64 b, u64 c) {
    u64 r; asm("fma.rn.f32x2 %0, %1, %2, %3;" : "=l"(r) : "l"(a), "l"(b), "l"(c)); return r;
}
__device__ __forceinline__ void cp16(uint32_t dst, const float4* src) {
    asm volatile("cp.async.cg.shared.global [%0], [%1], 16;" :: "r"(dst), "l"(src));
}
#define CP_COMMIT() asm volatile("cp.async.commit_group;" ::: "memory")
#define CP_WAIT0()  asm volatile("cp.async.wait_group 0;"  ::: "memory")
__device__ __forceinline__ float ldcv(const float* p) {
    float v; asm volatile("ld.global.cv.f32 %0, [%1];" : "=f"(v) : "l"(p)); return v;
}

// ---------------- smem layout (floats) ----------------
#define W1T 0          // 64 x 70   W1t[c*70+k] = W1[k*64+c]
#define W2T 4480       // 64 x 66
#define W3T 8704       // 128 x 66
#define B1O 17152
#define B2O 17216
#define B3O 17280
#define F0  17408      // pass item A feat 64x68
#define F1  21760      // pass item B feat 64x68
#define H1A 26112      // 64x66
#define H1B 30336
#define H2A 34560
#define H2B 38784
#define RO0 43008      // 16x128
#define RO1 45056
#define CDB 47104      // 4 x 256 cand d2
#define CIB 48128      // 4 x 256 cand idx (int)
#define NLB 49152      // 4 x 64 (int)
#define MS  49408      // ints [0]=seq [1..4]=cnt; floats +8..+19 = q[4][3]
#define SM_TOT 49428   // 197,712 bytes -> 1 CTA/SM

// ============================================================================
__global__ void __launch_bounds__(256)
init_kernel(const float* __restrict__ pos)
{
    int i = blockIdx.x * 256 + threadIdx.x;
    if (i == 0) g_ctr = 0;
    if (i < BATCH) g_prog[i] = 0;
    if (i < BATCH * NPTS) {
        const float* p = pos + (size_t)i * 3;
        g_pos4[i] = make_float4(p[0], p[1], p[2], 0.0f);
    }
}

// ============================================================================
__global__ void __launch_bounds__(256)
fused_kernel(const float* __restrict__ x, const float* __restrict__ pos,
             const float* __restrict__ W1, const float* __restrict__ b1,
             const float* __restrict__ W2, const float* __restrict__ b2,
             const float* __restrict__ W3, const float* __restrict__ b3,
             float* __restrict__ dout, int out_size)
{
    extern __shared__ float sm[];
    const int tid = threadIdx.x;
    const int lane = tid & 31, w = tid >> 5;

    // ======================= producer: FPS (blocks 0..7) ====================
    if (blockIdx.x < BATCH) {
        __shared__ u64 rd2[16];                 // [parity*8 + warp]
        float* sp = sm;                         // [NPTS*4]
        const int b = blockIdx.x;
        const float* pb = pos + (size_t)b * NPTS * 3;

        for (int i = tid; i < NPTS * 3; i += 256) {
            int p = i / 3, c = i - 3 * p;
            sp[4 * p + c] = pb[i];
        }
        __syncthreads();

        float px[16], py[16], pz[16], md[16];
#pragma unroll
        for (int j = 0; j < 16; j++) {
            int idx = j * 256 + tid;
            px[j] = sp[4 * idx]; py[j] = sp[4 * idx + 1]; pz[j] = sp[4 * idx + 2];
            md[j] = __int_as_float(0x7f800000);
        }

        if (tid == 0) {
            int g = b * MPTS;
            g_q[3*g] = sp[0]; g_q[3*g+1] = sp[1]; g_q[3*g+2] = sp[2];
            if (out_size >= BBASE) {
                dout[PBASE+3*g] = sp[0]; dout[PBASE+3*g+1] = sp[1]; dout[PBASE+3*g+2] = sp[2];
            }
            if (out_size >= TOTSEG) dout[BBASE+g] = (float)b;
            __threadfence();
            g_prog[b] = 1;
        }

        const float4* sp4 = (const float4*)sp;
        int cur = 0;

        for (int step = 1; step < MPTS; step++) {
            float4 L = sp4[cur];
            float bd = -1.0f; int bi = 0;
#pragma unroll
            for (int j = 0; j < 16; j++) {
                float dx = __fadd_rn(px[j], -L.x);
                float dy = __fadd_rn(py[j], -L.y);
                float dz = __fadd_rn(pz[j], -L.z);
                float d  = __fadd_rn(__fadd_rn(__fmul_rn(dx,dx), __fmul_rn(dy,dy)),
                                     __fmul_rn(dz,dz));
                float m = fminf(md[j], d);
                md[j] = m;
                if (m > bd) { bd = m; bi = j * 256 + tid; }
            }
            unsigned dbits = __float_as_uint(bd);
            unsigned mx   = rmax32(dbits);
            unsigned cand = (dbits == mx) ? (0xFFFFFFFFu - (unsigned)bi) : 0u;
            unsigned cmx  = rmax32(cand);
            if (lane == 0) rd2[(step & 1) * 8 + w] = ((u64)mx << 32) | (u64)cmx;
            __syncthreads();
            const u64* rr = &rd2[(step & 1) * 8];
            u64 best = rr[0];
#pragma unroll
            for (int i = 1; i < 8; i++) { u64 v = rr[i]; if (v > best) best = v; }
            cur = (int)(0xFFFFFFFFu - (unsigned)best);
            if (tid == 0) {
                int g = b * MPTS + step;
                float qx = sp[4*cur], qy = sp[4*cur+1], qz = sp[4*cur+2];
                g_q[3*g] = qx; g_q[3*g+1] = qy; g_q[3*g+2] = qz;
                if (out_size >= BBASE) {
                    dout[PBASE+3*g] = qx; dout[PBASE+3*g+1] = qy; dout[PBASE+3*g+2] = qz;
                }
                if (out_size >= TOTSEG) dout[BBASE+g] = (float)b;
                __threadfence();
                g_prog[b] = step + 1;
            }
        }
        __syncthreads();
    }

    // ======================= consumer setup =================================
    for (int idx = tid; idx < 67 * 64; idx += 256) {
        int k = idx >> 6, c = idx & 63;
        sm[W1T + c * 70 + k] = W1[idx];
    }
    for (int idx = tid; idx < 64 * 64; idx += 256) {
        int k = idx >> 6, c = idx & 63;
        sm[W2T + c * 66 + k] = W2[idx];
    }
    for (int idx = tid; idx < 64 * 128; idx += 256) {
        int k = idx >> 7, c = idx & 127;
        sm[W3T + c * 66 + k] = W3[idx];
    }
    if (tid < 64)  { sm[B1O + tid] = b1[tid]; sm[B2O + tid] = b2[tid]; }
    if (tid < 128)   sm[B3O + tid] = b3[tid];
    __syncthreads();

    int*   msi = (int*)(sm + MS);
    float* msf = sm + MS + 8;
    int*   cib = (int*)(sm + CIB);
    int*   nlb = (int*)(sm + NLB);

    const int rg = tid >> 4;     // 0..15 rows 4rg..4rg+3
    const int cg = tid & 15;     // 0..15
    const int e = tid >> 2, sub = tid & 3;
    const uint32_t smF0 = (uint32_t)__cvta_generic_to_shared(sm + F0);
    const uint32_t smF1 = (uint32_t)__cvta_generic_to_shared(sm + F1);
    const uint32_t rowoff = (uint32_t)((e * 68 + sub * 16) * sizeof(float));
    const float R2 = (float)(0.15 * 0.15);

    for (;;) {
        if (tid == 0) msi[0] = atomicAdd(&g_ctr, 1);
        __syncthreads();
        const int t = msi[0];
        if (t >= NTICK) break;
        const int b = t & 7, m0 = (t >> 3) * 4;
        const int gbase = b * MPTS + m0;

        if (tid == 0) {
            while (g_prog[b] <= m0 + 3) __nanosleep(128);
            __threadfence();
#pragma unroll
            for (int it = 0; it < 4; it++) {
                msf[it*3+0] = ldcv(&g_q[3*(gbase+it)]);
                msf[it*3+1] = ldcv(&g_q[3*(gbase+it)+1]);
                msf[it*3+2] = ldcv(&g_q[3*(gbase+it)+2]);
            }
            msi[1] = 0; msi[2] = 0; msi[3] = 0; msi[4] = 0;
        }
        __syncthreads();
        float qx[4], qy[4], qz[4];
#pragma unroll
        for (int it = 0; it < 4; it++) {
            qx[it] = msf[it*3]; qy[it] = msf[it*3+1]; qz[it] = msf[it*3+2];
        }

        // ---- radius scan: one pass, 4 centroids ----
#pragma unroll 2
        for (int i = tid; i < NPTS; i += 256) {
            float4 p = g_pos4[b * NPTS + i];
#pragma unroll
            for (int it = 0; it < 4; it++) {
                float dx = __fadd_rn(qx[it], -p.x);
                float dy = __fadd_rn(qy[it], -p.y);
                float dz = __fadd_rn(qz[it], -p.z);
                float d2 = __fadd_rn(__fadd_rn(__fmul_rn(dx,dx), __fmul_rn(dy,dy)),
                                     __fmul_rn(dz,dz));
                bool keep = (d2 <= R2);
                unsigned msk = __ballot_sync(0xffffffffu, keep);
                int basew = 0;
                if (lane == 0 && msk) basew = atomicAdd(&msi[1+it], __popc(msk));
                basew = __shfl_sync(0xffffffffu, basew, 0);
                if (keep) {
                    int ofs = basew + __popc(msk & ((1u << lane) - 1u));
                    if (ofs < CAP) { sm[CDB + it*CAP + ofs] = d2; cib[it*CAP + ofs] = i; }
                }
            }
        }
        __syncthreads();
        int cnt[4];
#pragma unroll
        for (int it = 0; it < 4; it++) {
            cnt[it] = msi[1+it]; if (cnt[it] > CAP) cnt[it] = CAP;
        }

        // ---- rank-select all 4 items in parallel (64 threads each) ----
        {
            const int item = tid >> 6;           // 0..3
            const int ht = tid & 63;
            const int c = cnt[item];
            const float* cd = sm + CDB + item*CAP;
            const int* cidx = cib + item*CAP;
            int* nlout = nlb + item*64;
            if (c > KNBR) {
                for (int s = ht; s < c; s += 64) {
                    float di = cd[s]; int ii = cidx[s];
                    int r = 0;
                    for (int j2 = 0; j2 < c; j2++) {
                        float dj = cd[j2];
                        r += (int)((dj < di) | ((dj == di) & (cidx[j2] < ii)));
                    }
                    if (r < KNBR) nlout[r] = ii;
                }
            } else {
                for (int s = ht; s < c; s += 64) nlout[s] = cidx[s];
            }
        }
        __syncthreads();
#pragma unroll
        for (int it = 0; it < 4; it++) if (cnt[it] > KNBR) cnt[it] = KNBR;

        // ======== two dual-item GEMM passes (identical to proven R13) =======
#pragma unroll 1
        for (int pass = 0; pass < 2; pass++) {
            const int iA = 2*pass, iB = iA + 1;
            const int g0 = gbase + iA, g1 = gbase + iB;
            const int cntA = cnt[iA], cntB = cnt[iB];
            int* nlA = nlb + iA*64;
            int* nlB = nlb + iB*64;
            const float qAx = qx[iA], qAy = qy[iA], qAz = qz[iA];
            const float qBx = qx[iB], qBy = qy[iB], qBz = qz[iB];

            // ---- gather both items' feat rows via cp.async ----
            {
                int j0 = nlA[(e < cntA) ? e : 0];
                int j1 = nlB[(e < cntB) ? e : 0];
                const float4* xr0 = (const float4*)(x + ((size_t)b * NPTS + j0) * FDIM) + sub * 4;
                const float4* xr1 = (const float4*)(x + ((size_t)b * NPTS + j1) * FDIM) + sub * 4;
                cp16(smF0 + rowoff +  0, xr0 + 0);
                cp16(smF0 + rowoff + 16, xr0 + 1);
                cp16(smF0 + rowoff + 32, xr0 + 2);
                cp16(smF0 + rowoff + 48, xr0 + 3);
                cp16(smF1 + rowoff +  0, xr1 + 0);
                cp16(smF1 + rowoff + 16, xr1 + 1);
                cp16(smF1 + rowoff + 32, xr1 + 2);
                cp16(smF1 + rowoff + 48, xr1 + 3);
                CP_COMMIT();
                if (sub == 0) {
                    float4 p0 = g_pos4[b * NPTS + j0];
                    float4 p1 = g_pos4[b * NPTS + j1];
                    float a0 = __fadd_rn(p0.x, -qAx);
                    float a1 = __fadd_rn(p0.y, -qAy);
                    float a2 = __fadd_rn(p0.z, -qAz);
                    float c0 = __fadd_rn(p1.x, -qBx);
                    float c1 = __fadd_rn(p1.y, -qBy);
                    float c2 = __fadd_rn(p1.z, -qBz);
                    CP_WAIT0();
                    sm[F0 + e*68 + 64] = a0; sm[F0 + e*68 + 65] = a1; sm[F0 + e*68 + 66] = a2;
                    sm[F1 + e*68 + 64] = c0; sm[F1 + e*68 + 65] = c1; sm[F1 + e*68 + 66] = c2;
                } else {
                    CP_WAIT0();
                }
            }
            __syncthreads();

            // ---- layer 1 (dual-item, W hoisted): K=67 = 33 k-pairs + tail ----
            {
                u64 acc0[4][4], acc1[4][4];
#pragma unroll
                for (int j = 0; j < 4; j++) {
                    float bb = sm[B1O + cg + 16*j];
#pragma unroll
                    for (int i = 0; i < 4; i++) {
                        acc0[i][j] = pk2(bb, 0.0f);
                        acc1[i][j] = pk2(bb, 0.0f);
                    }
                }
                for (int kp = 0; kp < 33; kp++) {
                    const int k = 2 * kp;
                    u64 a0[4], a1[4];
#pragma unroll
                    for (int i = 0; i < 4; i++) {
                        a0[i] = *(const u64*)(sm + F0 + (4*rg + i)*68 + k);
                        a1[i] = *(const u64*)(sm + F1 + (4*rg + i)*68 + k);
                    }
#pragma unroll
                    for (int j = 0; j < 4; j++) {
                        u64 wv = *(const u64*)(sm + W1T + (cg + 16*j)*70 + k);
#pragma unroll
                        for (int i = 0; i < 4; i++) {
                            acc0[i][j] = fma2(a0[i], wv, acc0[i][j]);
                            acc1[i][j] = fma2(a1[i], wv, acc1[i][j]);
                        }
                    }
                }
#pragma unroll
                for (int i = 0; i < 4; i++) {
                    float a66A = sm[F0 + (4*rg + i)*68 + 66];
                    float a66B = sm[F1 + (4*rg + i)*68 + 66];
#pragma unroll
                    for (int j = 0; j < 4; j++) {
                        float wk = sm[W1T + (cg + 16*j)*70 + 66];
                        float lo, hi;
                        up2(acc0[i][j], lo, hi);
                        float s0 = fmaf(a66A, wk, __fadd_rn(lo, hi));
                        sm[H1A + (4*rg + i)*66 + cg + 16*j] = fmaxf(s0, 0.0f);
                        up2(acc1[i][j], lo, hi);
                        float s1 = fmaf(a66B, wk, __fadd_rn(lo, hi));
                        sm[H1B + (4*rg + i)*66 + cg + 16*j] = fmaxf(s1, 0.0f);
                    }
                }
            }
            __syncthreads();

            // ---- layer 2 (dual-item, W hoisted): K=64 ----
            {
                u64 acc0[4][4], acc1[4][4];
#pragma unroll
                for (int j = 0; j < 4; j++) {
                    float bb = sm[B2O + cg + 16*j];
#pragma unroll
                    for (int i = 0; i < 4; i++) {
                        acc0[i][j] = pk2(bb, 0.0f);
                        acc1[i][j] = pk2(bb, 0.0f);
                    }
                }
                for (int kp = 0; kp < 32; kp++) {
                    const int k = 2 * kp;
                    u64 a0[4], a1[4];
#pragma unroll
                    for (int i = 0; i < 4; i++) {
                        a0[i] = *(const u64*)(sm + H1A + (4*rg + i)*66 + k);
                        a1[i] = *(const u64*)(sm + H1B + (4*rg + i)*66 + k);
                    }
#pragma unroll
                    for (int j = 0; j < 4; j++) {
                        u64 wv = *(const u64*)(sm + W2T + (cg + 16*j)*66 + k);
#pragma unroll
                        for (int i = 0; i < 4; i++) {
                            acc0[i][j] = fma2(a0[i], wv, acc0[i][j]);
                            acc1[i][j] = fma2(a1[i], wv, acc1[i][j]);
                        }
                    }
                }
#pragma unroll
                for (int i = 0; i < 4; i++)
#pragma unroll
                    for (int j = 0; j < 4; j++) {
                        float lo, hi;
                        up2(acc0[i][j], lo, hi);
                        sm[H2A + (4*rg + i)*66 + cg + 16*j] = fmaxf(__fadd_rn(lo, hi), 0.0f);
                        up2(acc1[i][j], lo, hi);
                        sm[H2B + (4*rg + i)*66 + cg + 16*j] = fmaxf(__fadd_rn(lo, hi), 0.0f);
                    }
            }
            __syncthreads();

            // ---- layer 3: per item sequential, K=64 ----
#pragma unroll 1
            for (int itx = 0; itx < 2; itx++) {
                const int hsrc = itx ? H2B : H2A;
                const int rdst = itx ? RO1 : RO0;
                u64 acc[4][8];
#pragma unroll
                for (int j = 0; j < 8; j++) {
                    float bb = sm[B3O + cg + 16*j];
#pragma unroll
                    for (int i = 0; i < 4; i++) acc[i][j] = pk2(bb, 0.0f);
                }
                for (int kp = 0; kp < 32; kp++) {
                    const int k = 2 * kp;
                    u64 a[4];
#pragma unroll
                    for (int i = 0; i < 4; i++)
                        a[i] = *(const u64*)(sm + hsrc + (4*rg + i)*66 + k);
#pragma unroll
                    for (int j = 0; j < 8; j++) {
                        u64 wv = *(const u64*)(sm + W3T + (cg + 16*j)*66 + k);
#pragma unroll
                        for (int i = 0; i < 4; i++)
                            acc[i][j] = fma2(a[i], wv, acc[i][j]);
                    }
                }
#pragma unroll
                for (int j = 0; j < 8; j++) {
                    float lo, hi; up2(acc[0][j], lo, hi);
                    float mm = fmaxf(__fadd_rn(lo, hi), 0.0f);
#pragma unroll
                    for (int i = 1; i < 4; i++) {
                        up2(acc[i][j], lo, hi);
                        mm = fmaxf(mm, fmaxf(__fadd_rn(lo, hi), 0.0f));
                    }
                    sm[rdst + rg*128 + cg + 16*j] = mm;
                }
            }
            __syncthreads();

            // ---- final reduce + store ----
            {
                const int item = tid >> 7;
                const int ht = tid & 127;
                const int rsrc = item ? RO1 : RO0;
                const int gg = item ? g1 : g0;
                float mm = sm[rsrc + ht];
#pragma unroll
                for (int r = 1; r < 16; r++) mm = fmaxf(mm, sm[rsrc + r*128 + ht]);
                dout[(size_t)gg * 128 + ht] = mm;
            }
            __syncthreads();   // protect F/H reuse next pass / next ticket
        }
    }
}

// ============================================================================
extern "C" void kernel_launch(void* const* d_in, const int* in_sizes, int n_in,
                              void* d_out, int out_size)
{
    const float* x   = (const float*)d_in[0];
    const float* pos = (const float*)d_in[1];
    const float* W1 = (const float*)d_in[3];
    const float* b1 = (const float*)d_in[4];
    const float* W2 = (const float*)d_in[5];
    const float* b2 = (const float*)d_in[6];
    const float* W3 = (const float*)d_in[7];
    const float* b3 = (const float*)d_in[8];
    float* out = (float*)d_out;

    const int fused_smem = SM_TOT * sizeof(float);   // 197,712 B -> 1 CTA/SM
    cudaFuncSetAttribute(fused_kernel, cudaFuncAttributeMaxDynamicSharedMemorySize,
                         fused_smem);

    init_kernel<<<(BATCH * NPTS + 255) / 256, 256>>>(pos);
    fused_kernel<<<148, 256, fused_smem>>>(x, pos, W1, b1, W2, b2, W3, b3,
                                           out, out_size);
}